// round 16
// baseline (speedup 1.0000x reference)
#include <cuda_runtime.h>
#include <cuda_fp16.h>
#include <math.h>
#include <stdint.h>

#define EMB_DIM 448
#define FEAT_DIM 64
#define DMODEL 512
#define NBATCH 8
#define SEQ 2048
#define MTOT (NBATCH * SEQ)
#define WMAT (DMODEL * DMODEL)
#define TRI_TILES 272  // sum over bm<32 of floor(bm/2)+1

// -------- scratch (device globals) --------
static __device__ __half g_xh[MTOT * DMODEL], g_xl[MTOT * DMODEL];
static __device__ __half g_hnh[MTOT * DMODEL], g_hnl[MTOT * DMODEL];
static __device__ __half g_th[MTOT * DMODEL], g_tl[MTOT * DMODEL];
static __device__ __half g_wfh[8 * WMAT], g_wfl[8 * WMAT];  // fp16 hi/lo weights
static __device__ __half g_qf[MTOT * DMODEL], g_kf[MTOT * DMODEL];
static __device__ __half g_vf[MTOT * DMODEL];
static __device__ __half g_sf[(size_t)NBATCH * SEQ * SEQ];
static __device__ float g_h[MTOT * DMODEL];
static __device__ float g_last[NBATCH * DMODEL], g_lt[NBATCH * DMODEL];

__device__ __forceinline__ uint32_t smem_u32(const void* p) {
    uint32_t a;
    asm("{ .reg .u64 t; cvta.to.shared.u64 t, %1; cvt.u32.u64 %0, t; }" : "=r"(a) : "l"(p));
    return a;
}
#define SWZ(o) ((o) ^ ((((uint32_t)(o)) >> 3) & 0x70))
// projection GEMM stage: Ahi 16K | Alo 16K | Bhi 16K | Blo 16K
#define OFF_ALO 16384u
#define OFF_BHI 32768u
#define OFF_BLO 49152u
#define STAGE_B 65536u
#define SMEM_TC 196608
// attention stages (64x128 CTA): A 8K + B 16K = 24K/stage, 3 stages -> 72K (3 CTA/SM)
#define AT_OFF_B 8192u
#define AT_STAGE 24576u
#define SMEM_AT 73728

__device__ __forceinline__ void ldm_x4(uint32_t* r, uint32_t addr) {
    asm volatile("ldmatrix.sync.aligned.m8n8.x4.shared.b16 {%0,%1,%2,%3}, [%4];"
                 : "=r"(r[0]), "=r"(r[1]), "=r"(r[2]), "=r"(r[3]) : "r"(addr));
}
__device__ __forceinline__ void ldm_x4t(uint32_t* r, uint32_t addr) {
    asm volatile("ldmatrix.sync.aligned.m8n8.x4.trans.shared.b16 {%0,%1,%2,%3}, [%4];"
                 : "=r"(r[0]), "=r"(r[1]), "=r"(r[2]), "=r"(r[3]) : "r"(addr));
}
__device__ __forceinline__ void mma16816h(float* c, const uint32_t* a, const uint32_t* b) {
    asm volatile(
        "mma.sync.aligned.m16n8k16.row.col.f32.f16.f16.f32 "
        "{%0,%1,%2,%3}, {%4,%5,%6,%7}, {%8,%9}, {%0,%1,%2,%3};"
        : "+f"(c[0]), "+f"(c[1]), "+f"(c[2]), "+f"(c[3])
        : "r"(a[0]), "r"(a[1]), "r"(a[2]), "r"(a[3]), "r"(b[0]), "r"(b[1]));
}
__device__ __forceinline__ void cpa16(uint32_t dst, const void* src) {
    asm volatile("cp.async.cg.shared.global [%0], [%1], 16;" :: "r"(dst), "l"(src));
}
#define CPA_COMMIT() asm volatile("cp.async.commit_group;" ::: "memory")

__device__ __forceinline__ void split4h(float4 f, uint2& h, uint2& l) {
    __half2 h0 = __floats2half2_rn(f.x, f.y);
    __half2 h1 = __floats2half2_rn(f.z, f.w);
    __half2 l0 = __floats2half2_rn(f.x - __half2float(h0.x), f.y - __half2float(h0.y));
    __half2 l1 = __floats2half2_rn(f.z - __half2float(h1.x), f.w - __half2float(h1.y));
    h.x = *(uint32_t*)&h0; h.y = *(uint32_t*)&h1;
    l.x = *(uint32_t*)&l0; l.y = *(uint32_t*)&l1;
}

// ============ fp16 split projection/MLP GEMM (512 thr, CTA 128x128) ============
// MODE: 0=bias->hi/lo, 1=bias+relu->hi/lo, 4=fused QKV (Q,K,V all fp16)
// PASSES==3 with MODE==4: V region (bn>=8) runs only 2 passes (drops Ah*Wl).
template <int MODE, int PASSES>
__global__ void __launch_bounds__(512) mma_gemm(const __half* __restrict__ Ah, const __half* __restrict__ Al,
                                                const __half* __restrict__ Bh, const __half* __restrict__ Bl,
                                                const float* __restrict__ bias, const float* __restrict__ bias2,
                                                const float* __restrict__ bias3,
                                                __half* __restrict__ Ch, __half* __restrict__ Cl,
                                                __half* __restrict__ C2h, __half* __restrict__ C3h) {
    extern __shared__ char smem[];
    const int tid = threadIdx.x, wid = tid >> 5, lane = tid & 31;
    const int bm = blockIdx.x, bn = blockIdx.y;
    const bool third = (PASSES == 3) && !(MODE == 4 && bn >= 8);  // V region: 2-pass
    Ah += (size_t)bm * 128 * DMODEL;
    Al += (size_t)bm * 128 * DMODEL;
    Bh += (size_t)bn * 128 * DMODEL;
    Bl += (size_t)bn * 128 * DMODEL;
    const int NC = DMODEL >> 6;  // 8
    const uint32_t sb = smem_u32(smem);
    const int wm = wid >> 2, wn = wid & 3;  // warp grid 4x4, warp tile 32x32
    const int lr = lane & 15, lc16 = (lane >> 4) * 16;

    float acc[2][4][4];
#pragma unroll
    for (int i = 0; i < 2; i++)
#pragma unroll
        for (int j = 0; j < 4; j++)
#pragma unroll
            for (int r = 0; r < 4; r++) acc[i][j][r] = 0.f;

#define STAGE_LOAD(S, CIDX) do { \
        uint32_t base_ = sb + (uint32_t)(S) * STAGE_B; \
        int koff_ = (CIDX) * 64; \
        _Pragma("unroll") \
        for (int j_ = 0; j_ < 2; j_++) { \
            int cc_ = tid + j_ * 512; \
            int r_ = cc_ >> 3, cg_ = cc_ & 7; \
            uint32_t so_ = SWZ((uint32_t)r_ * 128u + (uint32_t)cg_ * 16u); \
            size_t g_ = (size_t)r_ * DMODEL + koff_ + cg_ * 8; \
            cpa16(base_ + so_, Ah + g_); \
            cpa16(base_ + OFF_ALO + so_, Al + g_); \
            cpa16(base_ + OFF_BHI + so_, Bh + g_); \
            if (PASSES == 3) { if (third) cpa16(base_ + OFF_BLO + so_, Bl + g_); } \
        } \
        CPA_COMMIT(); \
    } while (0)

    uint32_t ah[2][2][4], al[2][2][4], bhf[2][4][2], blf[2][4][2];
#define LDFRAG(BUF, KS) do { \
        const uint32_t kb_ = (KS) * 32 + lc16; \
        _Pragma("unroll") \
        for (int mb_ = 0; mb_ < 2; mb_++) { \
            uint32_t ro_ = (uint32_t)(wm * 32 + mb_ * 16 + lr) * 128u + kb_; \
            ldm_x4(ah[BUF][mb_], base + SWZ(ro_)); \
            ldm_x4(al[BUF][mb_], base + OFF_ALO + SWZ(ro_)); \
        } \
        _Pragma("unroll") \
        for (int n2_ = 0; n2_ < 2; n2_++) { \
            uint32_t ro_ = (uint32_t)(wn * 32 + n2_ * 16 + lr) * 128u + kb_; \
            uint32_t t_[4]; \
            ldm_x4(t_, base + OFF_BHI + SWZ(ro_)); \
            bhf[BUF][n2_ * 2][0] = t_[0]; bhf[BUF][n2_ * 2][1] = t_[2]; \
            bhf[BUF][n2_ * 2 + 1][0] = t_[1]; bhf[BUF][n2_ * 2 + 1][1] = t_[3]; \
            if (PASSES == 3) { if (third) { \
                ldm_x4(t_, base + OFF_BLO + SWZ(ro_)); \
                blf[BUF][n2_ * 2][0] = t_[0]; blf[BUF][n2_ * 2][1] = t_[2]; \
                blf[BUF][n2_ * 2 + 1][0] = t_[1]; blf[BUF][n2_ * 2 + 1][1] = t_[3]; \
            } } \
        } \
    } while (0)

    STAGE_LOAD(0, 0);
    STAGE_LOAD(1, 1);

    for (int c = 0; c < NC; c++) {
        if (c + 1 < NC) asm volatile("cp.async.wait_group 1;" ::: "memory");
        else            asm volatile("cp.async.wait_group 0;" ::: "memory");
        __syncthreads();
        const uint32_t base = sb + (uint32_t)(((uint32_t)c) % 3u) * STAGE_B;
        LDFRAG(0, 0);
#pragma unroll
        for (int ks = 0; ks < 4; ks++) {
            const int cur = ks & 1;
            if (ks < 3) LDFRAG(!(ks & 1), ks + 1);
#pragma unroll
            for (int mb = 0; mb < 2; mb++)
#pragma unroll
                for (int nb = 0; nb < 4; nb++)
                    mma16816h(acc[mb][nb], ah[cur][mb], bhf[cur][nb]);
#pragma unroll
            for (int mb = 0; mb < 2; mb++)
#pragma unroll
                for (int nb = 0; nb < 4; nb++)
                    mma16816h(acc[mb][nb], al[cur][mb], bhf[cur][nb]);
            if (PASSES == 3) {
                if (third) {
#pragma unroll
                    for (int mb = 0; mb < 2; mb++)
#pragma unroll
                        for (int nb = 0; nb < 4; nb++)
                            mma16816h(acc[mb][nb], ah[cur][mb], blf[cur][nb]);
                }
            }
        }
        if (c + 2 < NC) STAGE_LOAD(((uint32_t)(c + 2)) % 3u, c + 2);
    }
#undef STAGE_LOAD
#undef LDFRAG

    const int g = lane >> 2, t4 = lane & 3;
    const int region = (MODE == 4) ? (bn >> 2) : 0;
#pragma unroll
    for (int mb = 0; mb < 2; mb++) {
        const int mbase = bm * 128 + wm * 32 + mb * 16 + g;
#pragma unroll
        for (int nb = 0; nb < 4; nb++) {
            const int n0 = bn * 128 + wn * 32 + nb * 8 + t4 * 2;
#pragma unroll
            for (int rr = 0; rr < 2; rr++) {
                const int m = mbase + rr * 8;
                float v0 = acc[mb][nb][rr * 2], v1 = acc[mb][nb][rr * 2 + 1];
                if (MODE == 0) { v0 += bias[n0]; v1 += bias[n0 + 1]; }
                if (MODE == 1) { v0 = fmaxf(v0 + bias[n0], 0.f); v1 = fmaxf(v1 + bias[n0 + 1], 0.f); }
                if (MODE == 0 || MODE == 1) {
                    __half2 hv = __floats2half2_rn(v0, v1);
                    __half2 lv = __floats2half2_rn(v0 - __half2float(hv.x), v1 - __half2float(hv.y));
                    *(__half2*)(Ch + (size_t)m * DMODEL + n0) = hv;
                    *(__half2*)(Cl + (size_t)m * DMODEL + n0) = lv;
                } else {  // MODE 4: region 0=Q, 1=K, 2=V — all fp16
                    const int nl = n0 - (region << 9);
                    if (region == 0) {
                        *(__half2*)(Ch + (size_t)m * DMODEL + nl) =
                            __floats2half2_rn(v0 + bias[nl], v1 + bias[nl + 1]);
                    } else if (region == 1) {
                        *(__half2*)(C2h + (size_t)m * DMODEL + nl) =
                            __floats2half2_rn(v0 + bias2[nl], v1 + bias2[nl + 1]);
                    } else {
                        *(__half2*)(C3h + (size_t)m * DMODEL + nl) =
                            __floats2half2_rn(v0 + bias3[nl], v1 + bias3[nl + 1]);
                    }
                }
            }
        }
    }
}

// ============ fp16 attention GEMM (CTA 64x128, 256 thr, 3 CTA/SM) ============
// MODE 0: scores = tril(QK^T)*scale -> fp16 ; grid.x = TRI_TILES (dense triangular)
// MODE 1: h = S @ V -> fp32, causal K bound; B = V [s][d] via ldmatrix.trans
template <int MODE>
__global__ void __launch_bounds__(256, 3) mma_attn(const __half* __restrict__ A, const __half* __restrict__ B,
                                                   __half* __restrict__ Sout, float* __restrict__ Hout,
                                                   int lda, int ldb,
                                                   size_t sA, size_t sB, size_t sC, float scale) {
    extern __shared__ char smem[];
    const int tid = threadIdx.x, wid = tid >> 5, lane = tid & 31;
    int bm, bn;
    if (MODE == 0) {
        // dense triangular enumeration, heavy (large bm) first
        int t = TRI_TILES - 1 - blockIdx.x;
        int u = (int)((sqrtf(4.0f * t + 1.0f) - 1.0f) * 0.5f);
        while (u * (u + 1) > t) u--;            // guard fp rounding
        while ((u + 1) * (u + 2) <= t) u++;
        int r = t - u * (u + 1);
        if (r <= u) { bm = 2 * u; bn = r; }
        else        { bm = 2 * u + 1; bn = r - (u + 1); }
    } else {
        bm = gridDim.x - 1 - blockIdx.x;
        bn = blockIdx.y;
    }
    const int bz = blockIdx.z;
    A += sA * bz + (size_t)bm * 64 * lda;
    if (MODE == 0) B += sB * bz + (size_t)bn * 128 * ldb;
    else           B += sB * bz + (size_t)bn * 128;
    const int NC = (MODE == 1) ? (bm + 1) : 8;
    const uint32_t sb = smem_u32(smem);
    const int wm = wid >> 2, wn = wid & 3;  // 2m x 4n
    const int lr = lane & 15, lc16 = (lane >> 4) * 16;

    float acc[2][4][4];
#pragma unroll
    for (int i = 0; i < 2; i++)
#pragma unroll
        for (int j = 0; j < 4; j++)
#pragma unroll
            for (int r = 0; r < 4; r++) acc[i][j][r] = 0.f;

#define AT_LOAD(S, CIDX) do { \
        uint32_t base_ = sb + (uint32_t)(S) * AT_STAGE; \
        int koff_ = (CIDX) * 64; \
        _Pragma("unroll") \
        for (int j_ = 0; j_ < 2; j_++) { \
            int cc_ = tid + j_ * 256; \
            int r_ = cc_ >> 3, cg_ = cc_ & 7; \
            cpa16(base_ + SWZ((uint32_t)r_ * 128u + (uint32_t)cg_ * 16u), \
                  A + (size_t)r_ * lda + koff_ + cg_ * 8); \
        } \
        _Pragma("unroll") \
        for (int j_ = 0; j_ < 4; j_++) { \
            int cc_ = tid + j_ * 256; \
            if (MODE == 0) { \
                int r_ = cc_ >> 3, cg_ = cc_ & 7; \
                cpa16(base_ + AT_OFF_B + SWZ((uint32_t)r_ * 128u + (uint32_t)cg_ * 16u), \
                      B + (size_t)r_ * ldb + koff_ + cg_ * 8); \
            } else { \
                int r_ = cc_ >> 4, sub_ = (cc_ >> 3) & 1, cg_ = cc_ & 7; \
                cpa16(base_ + AT_OFF_B + (uint32_t)sub_ * 8192u + \
                          SWZ((uint32_t)r_ * 128u + (uint32_t)cg_ * 16u), \
                      B + (size_t)(koff_ + r_) * DMODEL + sub_ * 64 + cg_ * 8); \
            } \
        } \
        CPA_COMMIT(); \
    } while (0)

    AT_LOAD(0, 0);
    if (NC > 1) AT_LOAD(1, 1);

    for (int c = 0; c < NC; c++) {
        if (c + 1 < NC) asm volatile("cp.async.wait_group 1;" ::: "memory");
        else            asm volatile("cp.async.wait_group 0;" ::: "memory");
        __syncthreads();
        const uint32_t base = sb + (uint32_t)(((uint32_t)c) % 3u) * AT_STAGE;
#pragma unroll
        for (int ks = 0; ks < 4; ks++) {
            const uint32_t kb = ks * 32 + lc16;
            uint32_t ah[2][4], bh[4][2];
#pragma unroll
            for (int mb = 0; mb < 2; mb++) {
                uint32_t ro = (uint32_t)(wm * 32 + mb * 16 + lr) * 128u + kb;
                ldm_x4(ah[mb], base + SWZ(ro));
            }
#pragma unroll
            for (int n2 = 0; n2 < 2; n2++) {
                uint32_t t[4];
                if (MODE == 0) {
                    uint32_t ro = (uint32_t)(wn * 32 + n2 * 16 + lr) * 128u + kb;
                    ldm_x4(t, base + AT_OFF_B + SWZ(ro));
                    bh[n2 * 2][0] = t[0]; bh[n2 * 2][1] = t[2];
                    bh[n2 * 2 + 1][0] = t[1]; bh[n2 * 2 + 1][1] = t[3];
                } else {
                    int d_loc = wn * 32 + n2 * 16 + ((lane >> 4) << 3);
                    uint32_t row = (uint32_t)(ks * 16 + (lane & 15));
                    uint32_t addr = base + AT_OFF_B + ((uint32_t)(d_loc >> 6)) * 8192u +
                                    SWZ(row * 128u + (uint32_t)(d_loc & 63) * 2u);
                    ldm_x4t(t, addr);
                    bh[n2 * 2][0] = t[0]; bh[n2 * 2][1] = t[1];
                    bh[n2 * 2 + 1][0] = t[2]; bh[n2 * 2 + 1][1] = t[3];
                }
            }
#pragma unroll
            for (int mb = 0; mb < 2; mb++)
#pragma unroll
                for (int nb = 0; nb < 4; nb++)
                    mma16816h(acc[mb][nb], ah[mb], bh[nb]);
        }
        if (c + 2 < NC) AT_LOAD(((uint32_t)(c + 2)) % 3u, c + 2);
    }
#undef AT_LOAD

    const int g = lane >> 2, t4 = lane & 3;
    if (MODE == 0) Sout += sC * bz;
    else           Hout += sC * bz;
#pragma unroll
    for (int mb = 0; mb < 2; mb++) {
        const int mbase = bm * 64 + wm * 32 + mb * 16 + g;
#pragma unroll
        for (int nb = 0; nb < 4; nb++) {
            const int n0 = bn * 128 + wn * 32 + nb * 8 + t4 * 2;
#pragma unroll
            for (int rr = 0; rr < 2; rr++) {
                const int m = mbase + rr * 8;
                float v0 = acc[mb][nb][rr * 2], v1 = acc[mb][nb][rr * 2 + 1];
                if (MODE == 0) {
                    v0 = (n0 <= m) ? v0 * scale : 0.f;
                    v1 = (n0 + 1 <= m) ? v1 * scale : 0.f;
                    *(__half2*)(Sout + (size_t)m * SEQ + n0) = __floats2half2_rn(v0, v1);
                } else {
                    *(float2*)(Hout + (size_t)m * DMODEL + n0) = make_float2(v0, v1);
                }
            }
        }
    }
}

// ---------------- fused gather + weight split (one launch) ----------------
__global__ __launch_bounds__(256) void prep_all(const int* __restrict__ seq,
                                                const float* __restrict__ feats,
                                                const float* __restrict__ emb,
                                                const float* __restrict__ Wq,
                                                const float* __restrict__ Wk,
                                                const float* __restrict__ Wv,
                                                const float* __restrict__ W1,
                                                const float* __restrict__ W2) {
    int bx = blockIdx.x;
    if (bx < MTOT * 128 / 256) {
        int i = bx * 256 + threadIdx.x;
        int row = i >> 7, d = (i & 127) << 2;
        float4 val;
        if (d < EMB_DIM) val = *(const float4*)(emb + (size_t)seq[row] * EMB_DIM + d);
        else val = *(const float4*)(feats + (size_t)row * FEAT_DIM + (d - EMB_DIM));
        uint2 h, l;
        split4h(val, h, l);
        *(uint2*)(g_xh + ((size_t)row << 9) + d) = h;
        *(uint2*)(g_xl + ((size_t)row << 9) + d) = l;
    } else {
        int wb = bx - MTOT * 128 / 256;
        int midx = wb >> 8;
        int blk = wb & 255;
        const float* src;
        switch (midx) {
            case 0: src = Wq; break;
            case 1: src = Wk; break;
            case 2: src = Wv; break;
            case 3: src = W1; break;
            case 4: src = W2; break;
            case 5: src = Wq + WMAT; break;
            case 6: src = Wk + WMAT; break;
            default: src = Wv + WMAT; break;
        }
        int i = (blk * 256 + threadIdx.x) << 2;
        float4 f = *(const float4*)(src + i);
        uint2 h, l;
        split4h(f, h, l);
        *(uint2*)(g_wfh + (size_t)midx * WMAT + i) = h;
        *(uint2*)(g_wfl + (size_t)midx * WMAT + i) = l;
    }
}

// fused stats + normalize. LAST=1: only emit last row into g_last
template <int LAST>
__global__ void norm_fused(const float* __restrict__ H) {
    const int b = blockIdx.x, tx = threadIdx.x, ty = threadIdx.y;
    const int d = blockIdx.y * 32 + tx;
    float sum = 0.f, sq = 0.f;
    for (int s = ty; s < SEQ; s += 8) {
        float v = H[(size_t)(b * SEQ + s) * DMODEL + d];
        sum += v; sq += v * v;
    }
    __shared__ float ss[8][32], s2[8][32], smean[32], srstd[32];
    ss[ty][tx] = sum; s2[ty][tx] = sq;
    __syncthreads();
    if (ty == 0) {
#pragma unroll
        for (int r = 1; r < 8; r++) { sum += ss[r][tx]; sq += s2[r][tx]; }
        float mean = sum * (1.0f / SEQ);
        float var = fmaxf((sq - sum * mean) * (1.0f / (SEQ - 1)), 0.0f);
        smean[tx] = mean;
        srstd[tx] = 1.0f / (sqrtf(var) + 2e-5f);
    }
    __syncthreads();
    const float mean = smean[tx], rstd = srstd[tx];
    if (LAST) {
        if (ty == 7) {
            float v = H[(size_t)(b * SEQ + SEQ - 1) * DMODEL + d];
            g_last[b * DMODEL + d] = (v - mean) * rstd;
        }
    } else {
        for (int s = ty; s < SEQ; s += 8) {
            float v = (H[(size_t)(b * SEQ + s) * DMODEL + d] - mean) * rstd;
            __half h = __float2half(v);
            __half l = __float2half(v - __half2float(h));
            g_hnh[(size_t)(b * SEQ + s) * DMODEL + d] = h;
            g_hnl[(size_t)(b * SEQ + s) * DMODEL + d] = l;
        }
    }
}

template <bool RELU>
__global__ void small_gemm(const float* __restrict__ A, const float* __restrict__ W,
                           const float* __restrict__ bias, float* __restrict__ C) {
    int i = blockIdx.x * 256 + threadIdx.x;  // 4096
    int m = i >> 9, n = i & 511;
    const float* a = A + (size_t)m * DMODEL;
    const float* w = W + (size_t)n * DMODEL;
    float s = 0.f;
#pragma unroll 8
    for (int k2 = 0; k2 < DMODEL; k2 += 4) {
        float4 av = *(const float4*)(a + k2), wv = *(const float4*)(w + k2);
        s += av.x * wv.x + av.y * wv.y + av.z * wv.z + av.w * wv.w;
    }
    s += bias[n];
    if (RELU) s = fmaxf(s, 0.0f);
    C[i] = s;
}

extern "C" void kernel_launch(void* const* d_in, const int* in_sizes, int n_in,
                              void* d_out, int out_size) {
    const int* seq = (const int*)d_in[0];
    const float* feats = (const float*)d_in[1];
    const float* emb = (const float*)d_in[2];
    const float* Wq = (const float*)d_in[3];  const float* bq = (const float*)d_in[4];
    const float* Wk = (const float*)d_in[5];  const float* bk = (const float*)d_in[6];
    const float* Wv = (const float*)d_in[7];  const float* bv = (const float*)d_in[8];
    const float* W1 = (const float*)d_in[9];  const float* b1 = (const float*)d_in[10];
    const float* W2 = (const float*)d_in[11]; const float* b2 = (const float*)d_in[12];
    float* out = (float*)d_out;

    cudaFuncSetAttribute(mma_gemm<0, 3>, cudaFuncAttributeMaxDynamicSharedMemorySize, SMEM_TC);
    cudaFuncSetAttribute(mma_gemm<1, 3>, cudaFuncAttributeMaxDynamicSharedMemorySize, SMEM_TC);
    cudaFuncSetAttribute(mma_gemm<4, 3>, cudaFuncAttributeMaxDynamicSharedMemorySize, SMEM_TC);
    cudaFuncSetAttribute(mma_gemm<4, 2>, cudaFuncAttributeMaxDynamicSharedMemorySize, SMEM_TC);
    cudaFuncSetAttribute(mma_attn<0>, cudaFuncAttributeMaxDynamicSharedMemorySize, SMEM_AT);
    cudaFuncSetAttribute(mma_attn<1>, cudaFuncAttributeMaxDynamicSharedMemorySize, SMEM_AT);

    void *pxh, *pxl, *phnh, *phnl, *pth, *ptl, *pwfh, *pwfl;
    void *pqf, *pkf, *pvf, *psf, *ph, *plast, *plt;
    cudaGetSymbolAddress(&pxh, g_xh);   cudaGetSymbolAddress(&pxl, g_xl);
    cudaGetSymbolAddress(&phnh, g_hnh); cudaGetSymbolAddress(&phnl, g_hnl);
    cudaGetSymbolAddress(&pth, g_th);   cudaGetSymbolAddress(&ptl, g_tl);
    cudaGetSymbolAddress(&pwfh, g_wfh); cudaGetSymbolAddress(&pwfl, g_wfl);
    cudaGetSymbolAddress(&pqf, g_qf);   cudaGetSymbolAddress(&pkf, g_kf);
    cudaGetSymbolAddress(&pvf, g_vf);   cudaGetSymbolAddress(&psf, g_sf);
    cudaGetSymbolAddress(&ph, g_h);
    cudaGetSymbolAddress(&plast, g_last); cudaGetSymbolAddress(&plt, g_lt);
    __half* xh = (__half*)pxh;   __half* xl = (__half*)pxl;
    __half* hnh = (__half*)phnh; __half* hnl = (__half*)phnl;
    __half* th = (__half*)pth;   __half* tl = (__half*)ptl;
    __half* wfh = (__half*)pwfh; __half* wfl = (__half*)pwfl;
    __half* qf = (__half*)pqf;   __half* kf = (__half*)pkf;
    __half* vf = (__half*)pvf;   __half* sf = (__half*)psf;
    float* h = (float*)ph;
    float* last = (float*)plast; float* lt = (float*)plt;

    const float scale = 0.044194173824159216f;  // 1/sqrt(512)

    prep_all<<<MTOT * 128 / 256 + 8 * 256, 256>>>(seq, feats, emb, Wq, Wk, Wv, W1, W2);

    const dim3 gqkv(MTOT / 128, 1536 / 128);        // 128 x 12
    const dim3 gw(MTOT / 128, DMODEL / 128);        // 128 x 4
    const dim3 gs(TRI_TILES, 1, NBATCH);            // dense triangular
    const dim3 ga(SEQ / 64, DMODEL / 128, NBATCH);  // 32 x 4 x 8

    for (int l = 0; l < 2; l++) {
        const int bo = l * DMODEL;
        const size_t mqkv = (size_t)(l ? 5 : 0) * WMAT;

        if (l == 0)
            mma_gemm<4, 3><<<gqkv, 512, SMEM_TC>>>(xh, xl, wfh + mqkv, wfl + mqkv,
                                                   bq + bo, bk + bo, bv + bo,
                                                   qf, nullptr, kf, vf);
        else
            mma_gemm<4, 2><<<gqkv, 512, SMEM_TC>>>(xh, xl, wfh + mqkv, wfl + mqkv,
                                                   bq + bo, bk + bo, bv + bo,
                                                   qf, nullptr, kf, vf);

        mma_attn<0><<<gs, 256, SMEM_AT>>>(qf, kf, sf, nullptr, DMODEL, DMODEL,
                                          (size_t)SEQ * DMODEL, (size_t)SEQ * DMODEL,
                                          (size_t)SEQ * SEQ, scale);
        mma_attn<1><<<ga, 256, SMEM_AT>>>(sf, vf, nullptr, h, SEQ, DMODEL,
                                          (size_t)SEQ * SEQ, (size_t)SEQ * DMODEL,
                                          (size_t)SEQ * DMODEL, 0.f);

        if (l == 0) {
            norm_fused<0><<<dim3(NBATCH, DMODEL / 32), dim3(32, 8)>>>(h);
            const size_t m1 = 3 * (size_t)WMAT, m2 = 4 * (size_t)WMAT;
            mma_gemm<1, 3><<<gw, 512, SMEM_TC>>>(hnh, hnl, wfh + m1, wfl + m1,
                                                 b1 + bo, nullptr, nullptr,
                                                 th, tl, nullptr, nullptr);
            mma_gemm<0, 3><<<gw, 512, SMEM_TC>>>(th, tl, wfh + m2, wfl + m2,
                                                 b2 + bo, nullptr, nullptr,
                                                 xh, xl, nullptr, nullptr);
        } else {
            norm_fused<1><<<dim3(NBATCH, DMODEL / 32), dim3(32, 8)>>>(h);
            small_gemm<true><<<16, 256>>>(last, W1 + (size_t)WMAT, b1 + bo, lt);
            small_gemm<false><<<16, 256>>>(lt, W2 + (size_t)WMAT, b2 + bo, out);
        }
    }
}